// round 10
// baseline (speedup 1.0000x reference)
#include <cuda_runtime.h>
#include <cuda_bf16.h>

// Weighted-MSE reduction, single fused kernel:
//   inv_freq[j] = sum(attr_num)/attr_num[j]
//   attr_w_i    = sum_j (attribute[i,j]==1) * inv_freq[j]
//   angle_w_i   = sum_j (1 - cos(ea[i,j]))
//   out         = mean_{i,d}( angle_w_i * attr_w_i * (inp-label)^2 )
//
// One warp per row, float4 streaming loads, double partials.
// Last-block-finishes pattern (threadfence + atomic ticket) does the final
// deterministic reduction and resets the ticket for graph replay.

#define ROWS_PER_BLOCK 16           // 16 warps/block, 1 row/warp
#define NTHREADS       (ROWS_PER_BLOCK * 32)
#define MAX_PARTIALS   16384

__device__ double        g_partials[MAX_PARTIALS];
__device__ unsigned int  g_ticket = 0;

__global__ __launch_bounds__(NTHREADS)
void loss_fused_kernel(const float* __restrict__ inp,
                       const float* __restrict__ label,
                       const float* __restrict__ ea,
                       const int*   __restrict__ attribute,
                       const float* __restrict__ attribute_num,
                       float* __restrict__ out,
                       int B, int D, int nblocks, double inv_count)
{
    __shared__ double s_warp[ROWS_PER_BLOCK];
    __shared__ bool   s_is_last;

    const int warp = threadIdx.x >> 5;
    const int lane = threadIdx.x & 31;
    const int row  = blockIdx.x * ROWS_PER_BLOCK + warp;

    double wsum_d = 0.0;

    if (row < B) {
        // --- per-row weight, computed by lane 0 and broadcast ---
        float weight = 0.0f;
        if (lane == 0) {
            float an0 = attribute_num[0], an1 = attribute_num[1],
                  an2 = attribute_num[2], an3 = attribute_num[3],
                  an4 = attribute_num[4], an5 = attribute_num[5];
            float an_sum = an0 + an1 + an2 + an3 + an4 + an5;

            const int* at = attribute + (size_t)row * 6;
            float attr_w = 0.0f;
            attr_w += (at[0] == 1) ? an_sum / an0 : 0.0f;
            attr_w += (at[1] == 1) ? an_sum / an1 : 0.0f;
            attr_w += (at[2] == 1) ? an_sum / an2 : 0.0f;
            attr_w += (at[3] == 1) ? an_sum / an3 : 0.0f;
            attr_w += (at[4] == 1) ? an_sum / an4 : 0.0f;
            attr_w += (at[5] == 1) ? an_sum / an5 : 0.0f;

            const float* e = ea + (size_t)row * 3;
            float angle_w = (1.0f - cosf(e[0]))
                          + (1.0f - cosf(e[1]))
                          + (1.0f - cosf(e[2]));
            weight = angle_w * attr_w;
        }
        weight = __shfl_sync(0xFFFFFFFFu, weight, 0);

        // --- streaming squared-error sum over the row (float4) ---
        const float4* ip = (const float4*)(inp   + (size_t)row * D);
        const float4* lp = (const float4*)(label + (size_t)row * D);
        const int nvec = D >> 2;   // D % 4 == 0 (D = 512)

        float acc = 0.0f;
        #pragma unroll 4
        for (int v = lane; v < nvec; v += 32) {
            float4 a = ip[v];
            float4 b = lp[v];
            float d0 = a.x - b.x, d1 = a.y - b.y,
                  d2 = a.z - b.z, d3 = a.w - b.w;
            acc = fmaf(d0, d0, acc);
            acc = fmaf(d1, d1, acc);
            acc = fmaf(d2, d2, acc);
            acc = fmaf(d3, d3, acc);
        }

        // warp reduce (fp32 within a row: plenty of precision)
        #pragma unroll
        for (int off = 16; off > 0; off >>= 1)
            acc += __shfl_xor_sync(0xFFFFFFFFu, acc, off);

        wsum_d = (double)weight * (double)acc;
    }

    if (lane == 0) s_warp[warp] = wsum_d;
    __syncthreads();

    if (threadIdx.x == 0) {
        double bsum = 0.0;
        #pragma unroll
        for (int w = 0; w < ROWS_PER_BLOCK; w++) bsum += s_warp[w];
        g_partials[blockIdx.x] = bsum;

        // publish partial, then take a ticket
        __threadfence();
        unsigned int t = atomicAdd(&g_ticket, 1u);
        s_is_last = (t == (unsigned int)(nblocks - 1));
    }
    __syncthreads();

    // --- last block performs the deterministic final reduction ---
    if (s_is_last) {
        __shared__ double s_red[NTHREADS];

        // volatile: force L2/global reads (no stale values; every writer
        // fenced before incrementing the ticket)
        const volatile double* vp = g_partials;

        double acc = 0.0;
        for (int i = threadIdx.x; i < nblocks; i += NTHREADS)
            acc += vp[i];                       // fixed per-thread order
        s_red[threadIdx.x] = acc;
        __syncthreads();

        #pragma unroll
        for (int stride = NTHREADS >> 1; stride > 0; stride >>= 1) {
            if (threadIdx.x < stride)
                s_red[threadIdx.x] += s_red[threadIdx.x + stride];
            __syncthreads();
        }

        if (threadIdx.x == 0) {
            out[0] = (float)(s_red[0] * inv_count);
            g_ticket = 0;                        // reset for next graph replay
        }
    }
}

extern "C" void kernel_launch(void* const* d_in, const int* in_sizes, int n_in,
                              void* d_out, int out_size)
{
    const float* inp       = (const float*)d_in[0];
    const float* label     = (const float*)d_in[1];
    const float* ea        = (const float*)d_in[2];
    const int*   attribute = (const int*)  d_in[3];
    const float* attr_num  = (const float*)d_in[4];

    const int B = in_sizes[2] / 3;          // ea is [B,3]
    const int D = in_sizes[0] / B;          // inp is [B,D]

    int nblocks = (B + ROWS_PER_BLOCK - 1) / ROWS_PER_BLOCK;   // 2048 for B=32768
    if (nblocks > MAX_PARTIALS) nblocks = MAX_PARTIALS;        // (not hit for this shape)

    double inv_count = 1.0 / ((double)B * (double)D);

    loss_fused_kernel<<<nblocks, NTHREADS>>>(
        inp, label, ea, attribute, attr_num, (float*)d_out,
        B, D, nblocks, inv_count);
}

// round 11
// speedup vs baseline: 1.0119x; 1.0119x over previous
#include <cuda_runtime.h>
#include <cuda_bf16.h>

// Weighted-MSE reduction, single fused persistent kernel.
//   inv_freq[j] = sum(attr_num)/attr_num[j]
//   attr_w_i    = sum_j (attribute[i,j]==1) * inv_freq[j]
//   angle_w_i   = sum_j (1 - cos(ea[i,j]))
//   out         = mean_{i,d}( angle_w_i * attr_w_i * (inp-label)^2 )
//
// Single wave: 592 CTAs (148 SMs x 4), 16 warps/CTA, warp-grid-stride rows.
// Weight inputs are warp-uniform -> every lane loads (broadcast) and computes
// the weight redundantly: no lane-0 serialization, no shfl broadcast, and the
// cos/div chain is consumed only AFTER the streaming loads are in flight.
// Last-block ticket pattern does the deterministic final reduction.

#define NTHREADS       512
#define WARPS_PER_CTA  16
#define NBLOCKS        592          // 148 SMs x 4 CTAs -> one wave
#define MAX_PARTIALS   1024

__device__ double        g_partials[MAX_PARTIALS];
__device__ unsigned int  g_ticket = 0;

__global__ __launch_bounds__(NTHREADS, 4)
void loss_fused_kernel(const float* __restrict__ inp,
                       const float* __restrict__ label,
                       const float* __restrict__ ea,
                       const int*   __restrict__ attribute,
                       const float* __restrict__ attribute_num,
                       float* __restrict__ out,
                       int B, int D, int nblocks, double inv_count)
{
    __shared__ double s_warp[WARPS_PER_CTA];
    __shared__ bool   s_is_last;

    const int lane   = threadIdx.x & 31;
    const int warp   = threadIdx.x >> 5;
    const int gwarp  = blockIdx.x * WARPS_PER_CTA + warp;
    const int nwarps = gridDim.x * WARPS_PER_CTA;
    const int nvec   = D >> 2;          // D % 4 == 0 (D = 512)

    // inverse-frequency weights: uniform, computed once per thread
    const float n0 = attribute_num[0], n1 = attribute_num[1],
                n2 = attribute_num[2], n3 = attribute_num[3],
                n4 = attribute_num[4], n5 = attribute_num[5];
    const float ns = n0 + n1 + n2 + n3 + n4 + n5;
    const float if0 = __fdividef(ns, n0), if1 = __fdividef(ns, n1),
                if2 = __fdividef(ns, n2), if3 = __fdividef(ns, n3),
                if4 = __fdividef(ns, n4), if5 = __fdividef(ns, n5);

    double wsum = 0.0;

    for (int row = gwarp; row < B; row += nwarps) {
        // --- issue warp-uniform weight-input loads (broadcast sectors) ---
        const float* e  = ea        + (size_t)row * 3;
        const int*   at = attribute + (size_t)row * 6;
        const float e0 = e[0], e1 = e[1], e2 = e[2];
        const int   a0 = at[0], a1 = at[1], a2 = at[2],
                    a3 = at[3], a4 = at[4], a5 = at[5];

        // --- streaming squared-error sum (float4, 4 indep accumulators) ---
        const float4* ip = (const float4*)(inp   + (size_t)row * D);
        const float4* lp = (const float4*)(label + (size_t)row * D);

        float acc0 = 0.0f, acc1 = 0.0f, acc2 = 0.0f, acc3 = 0.0f;
        int v = lane;
        for (; v + 96 < nvec; v += 128) {
            float4 x0 = __ldcs(ip + v),      y0 = __ldcs(lp + v);
            float4 x1 = __ldcs(ip + v + 32), y1 = __ldcs(lp + v + 32);
            float4 x2 = __ldcs(ip + v + 64), y2 = __ldcs(lp + v + 64);
            float4 x3 = __ldcs(ip + v + 96), y3 = __ldcs(lp + v + 96);

            float d;
            d = x0.x - y0.x; acc0 = fmaf(d, d, acc0);
            d = x0.y - y0.y; acc0 = fmaf(d, d, acc0);
            d = x0.z - y0.z; acc0 = fmaf(d, d, acc0);
            d = x0.w - y0.w; acc0 = fmaf(d, d, acc0);
            d = x1.x - y1.x; acc1 = fmaf(d, d, acc1);
            d = x1.y - y1.y; acc1 = fmaf(d, d, acc1);
            d = x1.z - y1.z; acc1 = fmaf(d, d, acc1);
            d = x1.w - y1.w; acc1 = fmaf(d, d, acc1);
            d = x2.x - y2.x; acc2 = fmaf(d, d, acc2);
            d = x2.y - y2.y; acc2 = fmaf(d, d, acc2);
            d = x2.z - y2.z; acc2 = fmaf(d, d, acc2);
            d = x2.w - y2.w; acc2 = fmaf(d, d, acc2);
            d = x3.x - y3.x; acc3 = fmaf(d, d, acc3);
            d = x3.y - y3.y; acc3 = fmaf(d, d, acc3);
            d = x3.z - y3.z; acc3 = fmaf(d, d, acc3);
            d = x3.w - y3.w; acc3 = fmaf(d, d, acc3);
        }
        for (; v < nvec; v += 32) {          // remainder (not hit for D=512)
            float4 x = __ldcs(ip + v), y = __ldcs(lp + v);
            float d;
            d = x.x - y.x; acc0 = fmaf(d, d, acc0);
            d = x.y - y.y; acc0 = fmaf(d, d, acc0);
            d = x.z - y.z; acc0 = fmaf(d, d, acc0);
            d = x.w - y.w; acc0 = fmaf(d, d, acc0);
        }

        float acc = (acc0 + acc1) + (acc2 + acc3);
        #pragma unroll
        for (int off = 16; off > 0; off >>= 1)
            acc += __shfl_xor_sync(0xFFFFFFFFu, acc, off);

        // --- weight arithmetic (consumed after loads; redundant per lane) ---
        float angle_w = (1.0f - cosf(e0)) + (1.0f - cosf(e1)) + (1.0f - cosf(e2));
        float attr_w  = (a0 == 1 ? if0 : 0.0f) + (a1 == 1 ? if1 : 0.0f)
                      + (a2 == 1 ? if2 : 0.0f) + (a3 == 1 ? if3 : 0.0f)
                      + (a4 == 1 ? if4 : 0.0f) + (a5 == 1 ? if5 : 0.0f);

        wsum += (double)(angle_w * attr_w) * (double)acc;
    }

    if (lane == 0) s_warp[warp] = wsum;
    __syncthreads();

    if (threadIdx.x == 0) {
        double bsum = 0.0;
        #pragma unroll
        for (int w = 0; w < WARPS_PER_CTA; w++) bsum += s_warp[w];
        g_partials[blockIdx.x] = bsum;

        __threadfence();
        unsigned int t = atomicAdd(&g_ticket, 1u);
        s_is_last = (t == (unsigned int)(nblocks - 1));
    }
    __syncthreads();

    // --- last block: deterministic final reduction + ticket reset ---
    if (s_is_last) {
        __shared__ double s_red[NTHREADS];

        const volatile double* vp = g_partials;
        double acc = 0.0;
        for (int i = threadIdx.x; i < nblocks; i += NTHREADS)
            acc += vp[i];
        s_red[threadIdx.x] = acc;
        __syncthreads();

        #pragma unroll
        for (int stride = NTHREADS >> 1; stride > 0; stride >>= 1) {
            if (threadIdx.x < stride)
                s_red[threadIdx.x] += s_red[threadIdx.x + stride];
            __syncthreads();
        }

        if (threadIdx.x == 0) {
            out[0] = (float)(s_red[0] * inv_count);
            g_ticket = 0;                    // reset for graph replay
        }
    }
}

extern "C" void kernel_launch(void* const* d_in, const int* in_sizes, int n_in,
                              void* d_out, int out_size)
{
    const float* inp       = (const float*)d_in[0];
    const float* label     = (const float*)d_in[1];
    const float* ea        = (const float*)d_in[2];
    const int*   attribute = (const int*)  d_in[3];
    const float* attr_num  = (const float*)d_in[4];

    const int B = in_sizes[2] / 3;          // ea is [B,3]
    const int D = in_sizes[0] / B;          // inp is [B,D]

    int nblocks = NBLOCKS;                  // single wave: 148 SMs x 4 CTAs
    if (nblocks > MAX_PARTIALS) nblocks = MAX_PARTIALS;

    double inv_count = 1.0 / ((double)B * (double)D);

    loss_fused_kernel<<<nblocks, NTHREADS>>>(
        inp, label, ea, attribute, attr_num, (float*)d_out,
        B, D, nblocks, inv_count);
}

// round 14
// speedup vs baseline: 1.2105x; 1.1963x over previous
#include <cuda_runtime.h>
#include <cuda_bf16.h>

// Weighted-MSE reduction, single fused persistent kernel.
//   inv_freq[j] = sum(attr_num)/attr_num[j]
//   attr_w_i    = sum_j (attribute[i,j]==1) * inv_freq[j]
//   angle_w_i   = sum_j (1 - cos(ea[i,j]))
//   out         = mean_{i,d}( angle_w_i * attr_w_i * (inp-label)^2 )
//
// Key fix vs prior rounds: 256 threads/CTA, 4 CTAs/SM -> 64 regs/thread, so
// the 8 LDG.128 per loop iteration (32 dest regs) stay concurrently in
// flight (true MLP-8) instead of being serialized by a 32-reg budget.
// Single wave: 592 CTAs (148 SMs x 4), warp-grid-stride over rows.
// Last-block ticket pattern does the deterministic final reduction.

#define NTHREADS       256
#define WARPS_PER_CTA  8
#define NBLOCKS        592          // 148 SMs x 4 CTAs -> one wave
#define MAX_PARTIALS   1024

__device__ double        g_partials[MAX_PARTIALS];
__device__ unsigned int  g_ticket = 0;

__global__ __launch_bounds__(NTHREADS, 4)
void loss_fused_kernel(const float* __restrict__ inp,
                       const float* __restrict__ label,
                       const float* __restrict__ ea,
                       const int*   __restrict__ attribute,
                       const float* __restrict__ attribute_num,
                       float* __restrict__ out,
                       int B, int D, int nblocks, double inv_count)
{
    __shared__ double s_warp[WARPS_PER_CTA];
    __shared__ bool   s_is_last;

    const int lane   = threadIdx.x & 31;
    const int warp   = threadIdx.x >> 5;
    const int gwarp  = blockIdx.x * WARPS_PER_CTA + warp;
    const int nwarps = gridDim.x * WARPS_PER_CTA;
    const int nvec   = D >> 2;          // D % 4 == 0 (D = 512)

    // inverse-frequency weights: uniform, computed once per thread
    const float n0 = attribute_num[0], n1 = attribute_num[1],
                n2 = attribute_num[2], n3 = attribute_num[3],
                n4 = attribute_num[4], n5 = attribute_num[5];
    const float ns = n0 + n1 + n2 + n3 + n4 + n5;
    const float if0 = __fdividef(ns, n0), if1 = __fdividef(ns, n1),
                if2 = __fdividef(ns, n2), if3 = __fdividef(ns, n3),
                if4 = __fdividef(ns, n4), if5 = __fdividef(ns, n5);

    double wsum = 0.0;

    for (int row = gwarp; row < B; row += nwarps) {
        // --- warp-uniform weight-input loads (broadcast sectors) ---
        const float* e  = ea        + (size_t)row * 3;
        const int*   at = attribute + (size_t)row * 6;
        const float e0 = e[0], e1 = e[1], e2 = e[2];
        const int   a0 = at[0], a1 = at[1], a2 = at[2],
                    a3 = at[3], a4 = at[4], a5 = at[5];

        // --- streaming squared-error sum: 8 LDG.128 in flight per warp ---
        const float4* ip = (const float4*)(inp   + (size_t)row * D);
        const float4* lp = (const float4*)(label + (size_t)row * D);

        float acc0 = 0.0f, acc1 = 0.0f, acc2 = 0.0f, acc3 = 0.0f;
        int v = lane;
        for (; v + 96 < nvec; v += 128) {
            float4 x0 = __ldcs(ip + v),      y0 = __ldcs(lp + v);
            float4 x1 = __ldcs(ip + v + 32), y1 = __ldcs(lp + v + 32);
            float4 x2 = __ldcs(ip + v + 64), y2 = __ldcs(lp + v + 64);
            float4 x3 = __ldcs(ip + v + 96), y3 = __ldcs(lp + v + 96);

            float d;
            d = x0.x - y0.x; acc0 = fmaf(d, d, acc0);
            d = x0.y - y0.y; acc0 = fmaf(d, d, acc0);
            d = x0.z - y0.z; acc0 = fmaf(d, d, acc0);
            d = x0.w - y0.w; acc0 = fmaf(d, d, acc0);
            d = x1.x - y1.x; acc1 = fmaf(d, d, acc1);
            d = x1.y - y1.y; acc1 = fmaf(d, d, acc1);
            d = x1.z - y1.z; acc1 = fmaf(d, d, acc1);
            d = x1.w - y1.w; acc1 = fmaf(d, d, acc1);
            d = x2.x - y2.x; acc2 = fmaf(d, d, acc2);
            d = x2.y - y2.y; acc2 = fmaf(d, d, acc2);
            d = x2.z - y2.z; acc2 = fmaf(d, d, acc2);
            d = x2.w - y2.w; acc2 = fmaf(d, d, acc2);
            d = x3.x - y3.x; acc3 = fmaf(d, d, acc3);
            d = x3.y - y3.y; acc3 = fmaf(d, d, acc3);
            d = x3.z - y3.z; acc3 = fmaf(d, d, acc3);
            d = x3.w - y3.w; acc3 = fmaf(d, d, acc3);
        }
        for (; v < nvec; v += 32) {          // remainder (not hit for D=512)
            float4 x = __ldcs(ip + v), y = __ldcs(lp + v);
            float d;
            d = x.x - y.x; acc0 = fmaf(d, d, acc0);
            d = x.y - y.y; acc0 = fmaf(d, d, acc0);
            d = x.z - y.z; acc0 = fmaf(d, d, acc0);
            d = x.w - y.w; acc0 = fmaf(d, d, acc0);
        }

        float acc = (acc0 + acc1) + (acc2 + acc3);
        #pragma unroll
        for (int off = 16; off > 0; off >>= 1)
            acc += __shfl_xor_sync(0xFFFFFFFFu, acc, off);

        // --- weight arithmetic (consumed after loads; redundant per lane) ---
        float angle_w = (1.0f - cosf(e0)) + (1.0f - cosf(e1)) + (1.0f - cosf(e2));
        float attr_w  = (a0 == 1 ? if0 : 0.0f) + (a1 == 1 ? if1 : 0.0f)
                      + (a2 == 1 ? if2 : 0.0f) + (a3 == 1 ? if3 : 0.0f)
                      + (a4 == 1 ? if4 : 0.0f) + (a5 == 1 ? if5 : 0.0f);

        wsum += (double)(angle_w * attr_w) * (double)acc;
    }

    if (lane == 0) s_warp[warp] = wsum;
    __syncthreads();

    if (threadIdx.x == 0) {
        double bsum = 0.0;
        #pragma unroll
        for (int w = 0; w < WARPS_PER_CTA; w++) bsum += s_warp[w];
        g_partials[blockIdx.x] = bsum;

        __threadfence();
        unsigned int t = atomicAdd(&g_ticket, 1u);
        s_is_last = (t == (unsigned int)(nblocks - 1));
    }
    __syncthreads();

    // --- last block: deterministic final reduction + ticket reset ---
    if (s_is_last) {
        __shared__ double s_red[NTHREADS];

        const volatile double* vp = g_partials;
        double acc = 0.0;
        for (int i = threadIdx.x; i < nblocks; i += NTHREADS)
            acc += vp[i];
        s_red[threadIdx.x] = acc;
        __syncthreads();

        #pragma unroll
        for (int stride = NTHREADS >> 1; stride > 0; stride >>= 1) {
            if (threadIdx.x < stride)
                s_red[threadIdx.x] += s_red[threadIdx.x + stride];
            __syncthreads();
        }

        if (threadIdx.x == 0) {
            out[0] = (float)(s_red[0] * inv_count);
            g_ticket = 0;                    // reset for graph replay
        }
    }
}

extern "C" void kernel_launch(void* const* d_in, const int* in_sizes, int n_in,
                              void* d_out, int out_size)
{
    const float* inp       = (const float*)d_in[0];
    const float* label     = (const float*)d_in[1];
    const float* ea        = (const float*)d_in[2];
    const int*   attribute = (const int*)  d_in[3];
    const float* attr_num  = (const float*)d_in[4];

    const int B = in_sizes[2] / 3;          // ea is [B,3]
    const int D = in_sizes[0] / B;          // inp is [B,D]

    int nblocks = NBLOCKS;                  // single wave: 148 SMs x 4 CTAs
    if (nblocks > MAX_PARTIALS) nblocks = MAX_PARTIALS;

    double inv_count = 1.0 / ((double)B * (double)D);

    loss_fused_kernel<<<nblocks, NTHREADS>>>(
        inp, label, ea, attribute, attr_num, (float*)d_out,
        B, D, nblocks, inv_count);
}